// round 9
// baseline (speedup 1.0000x reference)
#include <cuda_runtime.h>
#include <cuda_fp16.h>
#include <math.h>

#define N_NODES 1024
#define C_DIM   128
#define H_HEADS 8
#define D_HEAD  16
#define E_EDGES 32768
#define NN      (N_NODES * N_NODES)
#define SEQ_MAX 512
#define ATTN_BLOCKS 148
#define ATTN_THREADS 512

// Scratch (device globals; no allocation allowed)
__device__ float  g_conv[NN];               // fused conv output (scatter target)
__device__ float  g_Q[N_NODES * C_DIM];
__device__ float  g_K[N_NODES * C_DIM];
__device__ float  g_V[N_NODES * C_DIM];
__device__ __half g_P16[SEQ_MAX * C_DIM];   // fp16 P table, rows rotated by (s%8) segments
__device__ float  g_outpre[N_NODES * C_DIM];

// ---------------------------------------------------------------------------
__global__ void zero_conv_kernel() {
    int i = blockIdx.x * blockDim.x + threadIdx.x;   // NN/4 float4s
    ((float4*)g_conv)[i] = make_float4(0.f, 0.f, 0.f, 0.f);
}

// Fused scatter + 1x1 conv: adjflat[f] with f = 3*(r*1024+c)+t contributes
// conv_w[f/NN] * val at conv position f % NN.
__global__ void scatter_conv_kernel(const int* __restrict__ ei,
                                    const float* __restrict__ sign,
                                    const float* __restrict__ w,
                                    const float* __restrict__ cw) {
    int e = blockIdx.x * blockDim.x + threadIdx.x;
    if (e >= E_EDGES) return;
    int r = ei[e];
    int c = ei[E_EDGES + e];
    float vals[3] = { sign[2 * e], sign[2 * e + 1], w[e] };
    unsigned f0 = 3u * ((unsigned)r * N_NODES + (unsigned)c);
#pragma unroll
    for (int t = 0; t < 3; t++) {
        unsigned f = f0 + t;
        atomicAdd(g_conv + (f & (NN - 1)), cw[f >> 20] * vals[t]);
    }
}

// ---------------------------------------------------------------------------
// SGEMM body: O[n, c] = (bias? bias[c] : 0) + sum_k A[n,k] * W[c,k]
// 64x64 block tile, 4x4 register tile, K=128 in two 64-chunks.
// isPE: A is the sinusoid table computed inline, output goes to g_P16 as
// fp16 with per-row rotation by (s%8) 16-half segments.
#define KPAD 68
__device__ __forceinline__ void gemm64_body(const float* __restrict__ A,
                                            const float* __restrict__ W,
                                            const float* __restrict__ bias,
                                            float* __restrict__ O,
                                            bool isPE) {
    __shared__ float As[64][KPAD];
    __shared__ float Ws[64][KPAD];
    int tid = threadIdx.x;
    int n0 = blockIdx.x * 64;
    int c0 = blockIdx.y * 64;
    int tx = tid & 15;
    int ty = tid >> 4;

    float acc[4][4];
#pragma unroll
    for (int i = 0; i < 4; i++)
#pragma unroll
        for (int j = 0; j < 4; j++)
            acc[i][j] = 0.f;

    int m = tid & 63;
    int kq0 = tid >> 6;          // 0..3

    for (int kc = 0; kc < 2; kc++) {
        int k0 = kc * 64;
#pragma unroll
        for (int j = 0; j < 4; j++) {
            int kq = kq0 + j * 4;                    // 0..15
            float4 wv = *(const float4*)(W + (size_t)(c0 + m) * C_DIM + k0 + kq * 4);
            Ws[kq * 4 + 0][m] = wv.x; Ws[kq * 4 + 1][m] = wv.y;
            Ws[kq * 4 + 2][m] = wv.z; Ws[kq * 4 + 3][m] = wv.w;
            if (!isPE) {
                float4 av = *(const float4*)(A + (size_t)(n0 + m) * C_DIM + k0 + kq * 4);
                As[kq * 4 + 0][m] = av.x; As[kq * 4 + 1][m] = av.y;
                As[kq * 4 + 2][m] = av.z; As[kq * 4 + 3][m] = av.w;
            } else {
                int s = n0 + m;
#pragma unroll
                for (int u = 0; u < 4; u++) {
                    int c = k0 + kq * 4 + u;
                    int jj = c & 63;
                    float invf = exp2f(-(float)jj * 0.2076205059280929f);
                    float arg = (float)s * invf;
                    As[kq * 4 + u][m] = (c < 64) ? sinf(arg) : cosf(arg);
                }
            }
        }
        __syncthreads();
#pragma unroll
        for (int k = 0; k < 64; k++) {
            float4 a4 = *(const float4*)&As[k][ty * 4];
            float4 b4 = *(const float4*)&Ws[k][tx * 4];
            float a[4] = { a4.x, a4.y, a4.z, a4.w };
            float b[4] = { b4.x, b4.y, b4.z, b4.w };
#pragma unroll
            for (int i = 0; i < 4; i++)
#pragma unroll
                for (int j = 0; j < 4; j++)
                    acc[i][j] += a[i] * b[j];
        }
        __syncthreads();
    }
#pragma unroll
    for (int i = 0; i < 4; i++) {
        float b0 = bias ? bias[c0 + tx * 4 + 0] : 0.f;
        float b1 = bias ? bias[c0 + tx * 4 + 1] : 0.f;
        float b2 = bias ? bias[c0 + tx * 4 + 2] : 0.f;
        float b3 = bias ? bias[c0 + tx * 4 + 3] : 0.f;
        float o0 = acc[i][0] + b0, o1 = acc[i][1] + b1;
        float o2 = acc[i][2] + b2, o3 = acc[i][3] + b3;
        if (!isPE) {
            float4 o = make_float4(o0, o1, o2, o3);
            *(float4*)(O + (size_t)(n0 + ty * 4 + i) * C_DIM + c0 + tx * 4) = o;
        } else {
            int s = n0 + ty * 4 + i;
            int cc = c0 + tx * 4;
            int ccr = (cc + ((s & 7) << 4)) & 127;   // rotate by (s%8) segments
            __half2 h01 = __floats2half2_rn(o0, o1);
            __half2 h23 = __floats2half2_rn(o2, o3);
            *(__half2*)(g_P16 + s * C_DIM + ccr)     = h01;
            *(__half2*)(g_P16 + s * C_DIM + ccr + 2) = h23;
        }
    }
}

// Merged: z=0..2 -> Q/K/V GEMMs over x; z=3 -> P-table GEMM with inline PE.
__global__ void qkvp_gemm_kernel(const float* __restrict__ x,
                                 const float* __restrict__ Wq,
                                 const float* __restrict__ Wk,
                                 const float* __restrict__ Wv,
                                 const float* __restrict__ Wpos,
                                 const float* __restrict__ bpos) {
    int z = blockIdx.z;
    if (z == 3) {
        if (blockIdx.x >= SEQ_MAX / 64) return;   // only 512 rows
        gemm64_body(nullptr, Wpos, bpos, nullptr, true);
    } else {
        const float* W = (z == 0) ? Wq : (z == 1) ? Wk : Wv;
        float* O = (z == 0) ? g_Q : (z == 1) ? g_K : g_V;
        gemm64_body(x, W, nullptr, O, false);
    }
}

__global__ void out_gemm_kernel(const float* __restrict__ Wout,
                                float* __restrict__ out) {
    gemm64_body(g_outpre, Wout, nullptr, out, false);
}

// ---------------------------------------------------------------------------
// Persistent attention: 148 blocks x 512 threads; each block stages the fp16
// P table into smem once, then loops over (h, ag) tiles.
__global__ void __launch_bounds__(ATTN_THREADS)
attn_kernel(const int* __restrict__ seq,
            const float* __restrict__ param,
            const float* __restrict__ conv_b,
            float* __restrict__ attn_out) {
    extern __shared__ __half smP[];     // 512*128 halves = 128KB, rotated rows

    int tid = threadIdx.x;
    int lane = tid & 31;
    int wid = tid >> 5;                 // 0..15

    __shared__ float4 qs4[8][4];        // 8 q vectors (16 floats each)
    __shared__ int   srow[1024];        // seq row i
    __shared__ float probs[8][1024];    // 32KB: logits -> exp values
    __shared__ float wred[8][16];
    __shared__ float gmaxs[8];
    __shared__ float ginv[8];
    __shared__ float4 part4[16][8][4];  // [warp][r][d4]

    // Stage the whole P table once (coalesced float4 copy).
    {
        const float4* src = (const float4*)g_P16;   // 8192 float4s
        float4* dst = (float4*)smP;
#pragma unroll
        for (int j = 0; j < 16; j++)
            dst[tid + j * ATTN_THREADS] = src[tid + j * ATTN_THREADS];
    }

    const float SCALE = 0.0883883476483184f;  // 1/sqrt(128)
    float prm = param[0];
    float cb  = conv_b[0];

    for (int tile = blockIdx.x; tile < H_HEADS * 128; tile += ATTN_BLOCKS) {
        int h = tile >> 7;
        int ag = tile & 127;
        int a0 = ag * 8;

        __syncthreads();   // table staged (first iter) / prior tile fully done
        if (tid < 128) ((float*)qs4)[tid] = g_Q[h * 16384 + a0 * D_HEAD + tid];
        {
            int i = h * 128 + ag;
#pragma unroll
            for (int j = 0; j < 2; j++)
                srow[tid + j * ATTN_THREADS] = seq[(size_t)i * N_NODES + tid + j * ATTN_THREADS];
        }
        __syncthreads();

        float lmax[8];
#pragma unroll
        for (int r = 0; r < 8; r++) lmax[r] = -1e30f;

        const float4* Kh = (const float4*)(g_K + h * 16384);
#pragma unroll
        for (int t = 0; t < 2; t++) {
            int b = tid + t * ATTN_THREADS;
            float4 k0 = Kh[b * 4 + 0], k1 = Kh[b * 4 + 1];
            float4 k2 = Kh[b * 4 + 2], k3 = Kh[b * 4 + 3];
            int oct = b >> 3;
            int jj = b & 7;
#pragma unroll
            for (int r = 0; r < 8; r++) {
                int s = srow[r * 128 + oct];
                // rotated segment: physical start = ((jj + s) & 7) * 16 halves
                const __half* prow = smP + (s << 7) + (((jj + s) & 7) << 4);
                float4 ha = *(const float4*)(prow);        // halves 0..7
                float4 hb = *(const float4*)(prow + 8);    // halves 8..15
                const __half2* hA = (const __half2*)&ha;
                const __half2* hB = (const __half2*)&hb;
                float2 p0 = __half22float2(hA[0]);
                float2 p1 = __half22float2(hA[1]);
                float2 p2 = __half22float2(hA[2]);
                float2 p3 = __half22float2(hA[3]);
                float2 p4 = __half22float2(hB[0]);
                float2 p5 = __half22float2(hB[1]);
                float2 p6 = __half22float2(hB[2]);
                float2 p7 = __half22float2(hB[3]);
                float4 q0 = qs4[r][0], q1 = qs4[r][1], q2 = qs4[r][2], q3 = qs4[r][3];
                float cont = q0.x*k0.x + q0.y*k0.y + q0.z*k0.z + q0.w*k0.w
                           + q1.x*k1.x + q1.y*k1.y + q1.z*k1.z + q1.w*k1.w
                           + q2.x*k2.x + q2.y*k2.y + q2.z*k2.z + q2.w*k2.w
                           + q3.x*k3.x + q3.y*k3.y + q3.z*k3.z + q3.w*k3.w;
                float pos  = q0.x*p0.x + q0.y*p0.y + q0.z*p1.x + q0.w*p1.y
                           + q1.x*p2.x + q1.y*p2.y + q1.z*p3.x + q1.w*p3.y
                           + q2.x*p4.x + q2.y*p4.y + q2.z*p5.x + q2.w*p5.y
                           + q3.x*p6.x + q3.y*p6.y + q3.z*p7.x + q3.w*p7.y;
                float cv = g_conv[(size_t)(a0 + r) * N_NODES + b];
                float lg = (cont + pos) * SCALE + prm * (cv + cb);
                probs[r][b] = lg;
                lmax[r] = fmaxf(lmax[r], lg);
            }
        }
        // block max per r
#pragma unroll
        for (int r = 0; r < 8; r++) {
            float v = lmax[r];
#pragma unroll
            for (int o = 16; o > 0; o >>= 1) v = fmaxf(v, __shfl_xor_sync(~0u, v, o));
            if (lane == 0) wred[r][wid] = v;
        }
        __syncthreads();
        if (tid < 128) {
            int r = tid >> 4, k = tid & 15;
            float v = wred[r][k];
#pragma unroll
            for (int o = 8; o > 0; o >>= 1) v = fmaxf(v, __shfl_xor_sync(~0u, v, o));
            if (k == 0) gmaxs[r] = v;
        }
        __syncthreads();

        // exp + sum
        float lsum[8];
#pragma unroll
        for (int r = 0; r < 8; r++) lsum[r] = 0.f;
#pragma unroll
        for (int t = 0; t < 2; t++) {
            int b = tid + t * ATTN_THREADS;
#pragma unroll
            for (int r = 0; r < 8; r++) {
                float e = __expf(probs[r][b] - gmaxs[r]);
                probs[r][b] = e;
                lsum[r] += e;
            }
        }
#pragma unroll
        for (int r = 0; r < 8; r++) {
            float v = lsum[r];
#pragma unroll
            for (int o = 16; o > 0; o >>= 1) v += __shfl_xor_sync(~0u, v, o);
            if (lane == 0) wred[r][wid] = v;
        }
        __syncthreads();
        if (tid < 128) {
            int r = tid >> 4, k = tid & 15;
            float v = wred[r][k];
#pragma unroll
            for (int o = 8; o > 0; o >>= 1) v += __shfl_xor_sync(~0u, v, o);
            if (k == 0) ginv[r] = 1.f / v;
        }
        __syncthreads();

        // write normalized attn rows with streaming stores (probs keeps e)
        float inv[8];
#pragma unroll
        for (int r = 0; r < 8; r++) inv[r] = ginv[r];
        float* aout = attn_out + ((size_t)h << 20) + ((size_t)a0 << 10);
#pragma unroll
        for (int t = 0; t < 2; t++) {
            int b = tid + t * ATTN_THREADS;
#pragma unroll
            for (int r = 0; r < 8; r++)
                __stcs(&aout[((size_t)r << 10) + b], probs[r][b] * inv[r]);
        }

        // V phase: thread (bg, d4), bg = tid>>2 in [0,128), d4 = tid&3
        int d4 = tid & 3;
        int bg = tid >> 2;
        float4 acc[8];
#pragma unroll
        for (int r = 0; r < 8; r++) acc[r] = make_float4(0.f, 0.f, 0.f, 0.f);
        const float4* Vh = (const float4*)(g_V + h * 16384);
#pragma unroll 4
        for (int t = 0; t < 8; t++) {
            int b = bg + t * 128;
            float4 v4 = Vh[b * 4 + d4];
#pragma unroll
            for (int r = 0; r < 8; r++) {
                float e = probs[r][b];
                acc[r].x += e * v4.x; acc[r].y += e * v4.y;
                acc[r].z += e * v4.z; acc[r].w += e * v4.w;
            }
        }
#pragma unroll
        for (int r = 0; r < 8; r++) {
#pragma unroll
            for (int o = 16; o >= 4; o >>= 1) {
                acc[r].x += __shfl_xor_sync(~0u, acc[r].x, o);
                acc[r].y += __shfl_xor_sync(~0u, acc[r].y, o);
                acc[r].z += __shfl_xor_sync(~0u, acc[r].z, o);
                acc[r].w += __shfl_xor_sync(~0u, acc[r].w, o);
            }
        }
        if (lane < 4) {
#pragma unroll
            for (int r = 0; r < 8; r++) part4[wid][r][d4] = acc[r];
        }
        __syncthreads();
        if (tid < 128) {
            int r = tid >> 4, d = tid & 15;
            int dq = d >> 2, cmp = d & 3;
            float s = 0.f;
#pragma unroll
            for (int w = 0; w < 16; w++) s += ((const float*)&part4[w][r][dq])[cmp];
            g_outpre[h * 16384 + (a0 + r) * D_HEAD + d] = s * ginv[r];
        }
    }
}

// ---------------------------------------------------------------------------
extern "C" void kernel_launch(void* const* d_in, const int* in_sizes, int n_in,
                              void* d_out, int out_size) {
    const float* x      = (const float*)d_in[0];
    const float* sign   = (const float*)d_in[1];
    const float* weight = (const float*)d_in[2];
    const float* Wq     = (const float*)d_in[3];
    const float* Wk     = (const float*)d_in[4];
    const float* Wv     = (const float*)d_in[5];
    const float* Wout   = (const float*)d_in[6];
    const float* Wpos   = (const float*)d_in[7];
    const float* bpos   = (const float*)d_in[8];
    const float* conv_w = (const float*)d_in[9];
    const float* conv_b = (const float*)d_in[10];
    const float* param  = (const float*)d_in[11];
    const int*   seq    = (const int*)d_in[12];
    const int*   ei     = (const int*)d_in[13];

    float* out  = (float*)d_out;              // [1024, 128]
    float* attn = out + N_NODES * C_DIM;      // [1, 8, 1024, 1024]

    const int P_SMEM = SEQ_MAX * C_DIM * (int)sizeof(__half);  // 128KB dynamic
    static bool attr_set = false;
    if (!attr_set) {
        cudaFuncSetAttribute(attn_kernel,
                             cudaFuncAttributeMaxDynamicSharedMemorySize, P_SMEM);
        attr_set = true;
    }

    zero_conv_kernel<<<NN / 4 / 256, 256>>>();
    scatter_conv_kernel<<<E_EDGES / 256, 256>>>(ei, sign, weight, conv_w);
    qkvp_gemm_kernel<<<dim3(16, 2, 4), 256>>>(x, Wq, Wk, Wv, Wpos, bpos);
    attn_kernel<<<ATTN_BLOCKS, ATTN_THREADS, P_SMEM>>>(seq, param, conv_b, attn);
    out_gemm_kernel<<<dim3(16, 2), 256>>>(Wout, out);
}

// round 10
// speedup vs baseline: 1.2165x; 1.2165x over previous
#include <cuda_runtime.h>
#include <cuda_fp16.h>
#include <math.h>

#define N_NODES 1024
#define C_DIM   128
#define H_HEADS 8
#define D_HEAD  16
#define E_EDGES 32768
#define NN      (N_NODES * N_NODES)
#define SEQ_MAX 512
#define ATTN_BLOCKS 148

// Scratch (device globals; no allocation allowed)
__device__ float  g_conv[NN];               // fused conv output (scatter target)
__device__ float  g_Q[N_NODES * C_DIM];
__device__ float  g_K[N_NODES * C_DIM];
__device__ __half g_K16[N_NODES * C_DIM];   // fp16 K (rows = 32B)
__device__ float  g_V[N_NODES * C_DIM];
__device__ __half g_P16[SEQ_MAX * C_DIM];   // fp16 P table, rows rotated by (s%8) segments
__device__ float  g_outpre[N_NODES * C_DIM];

// ---------------------------------------------------------------------------
__global__ void zero_conv_kernel() {
    int i = blockIdx.x * blockDim.x + threadIdx.x;   // NN/4 float4s
    ((float4*)g_conv)[i] = make_float4(0.f, 0.f, 0.f, 0.f);
}

// Fused scatter + 1x1 conv: adjflat[f] with f = 3*(r*1024+c)+t contributes
// conv_w[f/NN] * val at conv position f % NN.
__global__ void scatter_conv_kernel(const int* __restrict__ ei,
                                    const float* __restrict__ sign,
                                    const float* __restrict__ w,
                                    const float* __restrict__ cw) {
    int e = blockIdx.x * blockDim.x + threadIdx.x;
    if (e >= E_EDGES) return;
    int r = ei[e];
    int c = ei[E_EDGES + e];
    float vals[3] = { sign[2 * e], sign[2 * e + 1], w[e] };
    unsigned f0 = 3u * ((unsigned)r * N_NODES + (unsigned)c);
#pragma unroll
    for (int t = 0; t < 3; t++) {
        unsigned f = f0 + t;
        atomicAdd(g_conv + (f & (NN - 1)), cw[f >> 20] * vals[t]);
    }
}

// ---------------------------------------------------------------------------
// SGEMM body: O[n, c] = (bias? bias[c] : 0) + sum_k A[n,k] * W[c,k]
// 64x64 block tile, 4x4 register tile, K=128 in two 64-chunks.
// isPE: A is the sinusoid table computed inline, output goes to g_P16 as
// fp16 with per-row rotation by (s%8) 16-half segments.
// toHalfK: additionally writes an fp16 copy to g_K16.
#define KPAD 68
__device__ __forceinline__ void gemm64_body(const float* __restrict__ A,
                                            const float* __restrict__ W,
                                            const float* __restrict__ bias,
                                            float* __restrict__ O,
                                            bool isPE, bool toHalfK) {
    __shared__ float As[64][KPAD];
    __shared__ float Ws[64][KPAD];
    int tid = threadIdx.x;
    int n0 = blockIdx.x * 64;
    int c0 = blockIdx.y * 64;
    int tx = tid & 15;
    int ty = tid >> 4;

    float acc[4][4];
#pragma unroll
    for (int i = 0; i < 4; i++)
#pragma unroll
        for (int j = 0; j < 4; j++)
            acc[i][j] = 0.f;

    int m = tid & 63;
    int kq0 = tid >> 6;          // 0..3

    for (int kc = 0; kc < 2; kc++) {
        int k0 = kc * 64;
#pragma unroll
        for (int j = 0; j < 4; j++) {
            int kq = kq0 + j * 4;                    // 0..15
            float4 wv = *(const float4*)(W + (size_t)(c0 + m) * C_DIM + k0 + kq * 4);
            Ws[kq * 4 + 0][m] = wv.x; Ws[kq * 4 + 1][m] = wv.y;
            Ws[kq * 4 + 2][m] = wv.z; Ws[kq * 4 + 3][m] = wv.w;
            if (!isPE) {
                float4 av = *(const float4*)(A + (size_t)(n0 + m) * C_DIM + k0 + kq * 4);
                As[kq * 4 + 0][m] = av.x; As[kq * 4 + 1][m] = av.y;
                As[kq * 4 + 2][m] = av.z; As[kq * 4 + 3][m] = av.w;
            } else {
                int s = n0 + m;
#pragma unroll
                for (int u = 0; u < 4; u++) {
                    int c = k0 + kq * 4 + u;
                    int jj = c & 63;
                    float invf = exp2f(-(float)jj * 0.2076205059280929f);
                    float arg = (float)s * invf;
                    As[kq * 4 + u][m] = (c < 64) ? sinf(arg) : cosf(arg);
                }
            }
        }
        __syncthreads();
#pragma unroll
        for (int k = 0; k < 64; k++) {
            float4 a4 = *(const float4*)&As[k][ty * 4];
            float4 b4 = *(const float4*)&Ws[k][tx * 4];
            float a[4] = { a4.x, a4.y, a4.z, a4.w };
            float b[4] = { b4.x, b4.y, b4.z, b4.w };
#pragma unroll
            for (int i = 0; i < 4; i++)
#pragma unroll
                for (int j = 0; j < 4; j++)
                    acc[i][j] += a[i] * b[j];
        }
        __syncthreads();
    }
#pragma unroll
    for (int i = 0; i < 4; i++) {
        float b0 = bias ? bias[c0 + tx * 4 + 0] : 0.f;
        float b1 = bias ? bias[c0 + tx * 4 + 1] : 0.f;
        float b2 = bias ? bias[c0 + tx * 4 + 2] : 0.f;
        float b3 = bias ? bias[c0 + tx * 4 + 3] : 0.f;
        float o0 = acc[i][0] + b0, o1 = acc[i][1] + b1;
        float o2 = acc[i][2] + b2, o3 = acc[i][3] + b3;
        if (!isPE) {
            size_t idx = (size_t)(n0 + ty * 4 + i) * C_DIM + c0 + tx * 4;
            *(float4*)(O + idx) = make_float4(o0, o1, o2, o3);
            if (toHalfK) {
                *(__half2*)(g_K16 + idx)     = __floats2half2_rn(o0, o1);
                *(__half2*)(g_K16 + idx + 2) = __floats2half2_rn(o2, o3);
            }
        } else {
            int s = n0 + ty * 4 + i;
            int cc = c0 + tx * 4;
            int ccr = (cc + ((s & 7) << 4)) & 127;   // rotate by (s%8) segments
            *(__half2*)(g_P16 + s * C_DIM + ccr)     = __floats2half2_rn(o0, o1);
            *(__half2*)(g_P16 + s * C_DIM + ccr + 2) = __floats2half2_rn(o2, o3);
        }
    }
}

// Merged: z=0..2 -> Q/K/V GEMMs over x; z=3 -> P-table GEMM with inline PE.
__global__ void qkvp_gemm_kernel(const float* __restrict__ x,
                                 const float* __restrict__ Wq,
                                 const float* __restrict__ Wk,
                                 const float* __restrict__ Wv,
                                 const float* __restrict__ Wpos,
                                 const float* __restrict__ bpos) {
    int z = blockIdx.z;
    if (z == 3) {
        if (blockIdx.x >= SEQ_MAX / 64) return;   // only 512 rows
        gemm64_body(nullptr, Wpos, bpos, nullptr, true, false);
    } else {
        const float* W = (z == 0) ? Wq : (z == 1) ? Wk : Wv;
        float* O = (z == 0) ? g_Q : (z == 1) ? g_K : g_V;
        gemm64_body(x, W, nullptr, O, false, z == 1);
    }
}

__global__ void out_gemm_kernel(const float* __restrict__ Wout,
                                float* __restrict__ out) {
    gemm64_body(g_outpre, Wout, nullptr, out, false, false);
}

// ---------------------------------------------------------------------------
// Persistent attention: 148 blocks; each stages the fp16 P table into smem
// once, then loops over (h, ag) tiles. 256 threads. K read in fp16.
__global__ void attn_kernel(const int* __restrict__ seq,
                            const float* __restrict__ param,
                            const float* __restrict__ conv_b,
                            float* __restrict__ attn_out) {
    extern __shared__ __half smP[];     // 512*128 halves = 128KB, rotated rows

    int tid = threadIdx.x;
    int lane = tid & 31;
    int wid = tid >> 5;

    __shared__ float4 qs4[8][4];        // 8 q vectors (16 floats each)
    __shared__ int   srow[1024];        // seq row i
    __shared__ float probs[8][1024];    // 32KB: logits -> exp values
    __shared__ float wred[8][8];
    __shared__ float gmaxs[8];
    __shared__ float ginv[8];
    __shared__ float4 part4[8][8][4];   // [warp][r][d4]

    // Stage the whole P table once (coalesced float4 copy).
    {
        const float4* src = (const float4*)g_P16;   // 8192 float4s
        float4* dst = (float4*)smP;
#pragma unroll
        for (int j = 0; j < 32; j++)
            dst[tid + j * 256] = src[tid + j * 256];
    }

    const float SCALE = 0.0883883476483184f;  // 1/sqrt(128)
    float prm = param[0];
    float cb  = conv_b[0];

    for (int tile = blockIdx.x; tile < H_HEADS * 128; tile += ATTN_BLOCKS) {
        int h = tile >> 7;
        int ag = tile & 127;
        int a0 = ag * 8;

        __syncthreads();   // table staged (first iter) / prior tile fully done
        if (tid < 128) ((float*)qs4)[tid] = g_Q[h * 16384 + a0 * D_HEAD + tid];
        {
            int i = h * 128 + ag;
#pragma unroll
            for (int j = 0; j < 4; j++)
                srow[tid + j * 256] = seq[(size_t)i * N_NODES + tid + j * 256];
        }
        __syncthreads();

        float lmax[8];
#pragma unroll
        for (int r = 0; r < 8; r++) lmax[r] = -1e30f;

        const __half* K16h = g_K16 + h * 16384;
#pragma unroll
        for (int t = 0; t < 4; t++) {
            int b = tid + t * 256;
            // fp16 K row: 32B = 2x float4-of-halves
            float4 ka = *(const float4*)(K16h + b * 16);
            float4 kb = *(const float4*)(K16h + b * 16 + 8);
            const __half2* kA = (const __half2*)&ka;
            const __half2* kB = (const __half2*)&kb;
            float2 km0 = __half22float2(kA[0]);
            float2 km1 = __half22float2(kA[1]);
            float2 km2 = __half22float2(kA[2]);
            float2 km3 = __half22float2(kA[3]);
            float2 km4 = __half22float2(kB[0]);
            float2 km5 = __half22float2(kB[1]);
            float2 km6 = __half22float2(kB[2]);
            float2 km7 = __half22float2(kB[3]);
            int oct = b >> 3;
            int jj = b & 7;
#pragma unroll
            for (int r = 0; r < 8; r++) {
                int s = srow[r * 128 + oct];
                // rotated segment: physical start = ((jj + s) & 7) * 16 halves
                const __half* prow = smP + (s << 7) + (((jj + s) & 7) << 4);
                float4 ha = *(const float4*)(prow);        // halves 0..7
                float4 hb = *(const float4*)(prow + 8);    // halves 8..15
                const __half2* hA = (const __half2*)&ha;
                const __half2* hB = (const __half2*)&hb;
                float2 p0 = __half22float2(hA[0]);
                float2 p1 = __half22float2(hA[1]);
                float2 p2 = __half22float2(hA[2]);
                float2 p3 = __half22float2(hA[3]);
                float2 p4 = __half22float2(hB[0]);
                float2 p5 = __half22float2(hB[1]);
                float2 p6 = __half22float2(hB[2]);
                float2 p7 = __half22float2(hB[3]);
                float4 q0 = qs4[r][0], q1 = qs4[r][1], q2 = qs4[r][2], q3 = qs4[r][3];
                float cont = q0.x*km0.x + q0.y*km0.y + q0.z*km1.x + q0.w*km1.y
                           + q1.x*km2.x + q1.y*km2.y + q1.z*km3.x + q1.w*km3.y
                           + q2.x*km4.x + q2.y*km4.y + q2.z*km5.x + q2.w*km5.y
                           + q3.x*km6.x + q3.y*km6.y + q3.z*km7.x + q3.w*km7.y;
                float pos  = q0.x*p0.x + q0.y*p0.y + q0.z*p1.x + q0.w*p1.y
                           + q1.x*p2.x + q1.y*p2.y + q1.z*p3.x + q1.w*p3.y
                           + q2.x*p4.x + q2.y*p4.y + q2.z*p5.x + q2.w*p5.y
                           + q3.x*p6.x + q3.y*p6.y + q3.z*p7.x + q3.w*p7.y;
                float cv = g_conv[(size_t)(a0 + r) * N_NODES + b];
                float lg = (cont + pos) * SCALE + prm * (cv + cb);
                probs[r][b] = lg;
                lmax[r] = fmaxf(lmax[r], lg);
            }
        }
        // block max per r
#pragma unroll
        for (int r = 0; r < 8; r++) {
            float v = lmax[r];
#pragma unroll
            for (int o = 16; o > 0; o >>= 1) v = fmaxf(v, __shfl_xor_sync(~0u, v, o));
            if (lane == 0) wred[r][wid] = v;
        }
        __syncthreads();
        if (tid < 64) {
            int r = tid >> 3, k = tid & 7;
            float v = wred[r][k];
#pragma unroll
            for (int o = 4; o > 0; o >>= 1) v = fmaxf(v, __shfl_xor_sync(~0u, v, o));
            if (k == 0) gmaxs[r] = v;
        }
        __syncthreads();

        // exp + sum
        float lsum[8];
#pragma unroll
        for (int r = 0; r < 8; r++) lsum[r] = 0.f;
#pragma unroll
        for (int t = 0; t < 4; t++) {
            int b = tid + t * 256;
#pragma unroll
            for (int r = 0; r < 8; r++) {
                float e = __expf(probs[r][b] - gmaxs[r]);
                probs[r][b] = e;
                lsum[r] += e;
            }
        }
#pragma unroll
        for (int r = 0; r < 8; r++) {
            float v = lsum[r];
#pragma unroll
            for (int o = 16; o > 0; o >>= 1) v += __shfl_xor_sync(~0u, v, o);
            if (lane == 0) wred[r][wid] = v;
        }
        __syncthreads();
        if (tid < 64) {
            int r = tid >> 3, k = tid & 7;
            float v = wred[r][k];
#pragma unroll
            for (int o = 4; o > 0; o >>= 1) v += __shfl_xor_sync(~0u, v, o);
            if (k == 0) ginv[r] = 1.f / v;
        }
        __syncthreads();

        // write normalized attn rows with streaming stores (probs keeps e)
        float inv[8];
#pragma unroll
        for (int r = 0; r < 8; r++) inv[r] = ginv[r];
        float* aout = attn_out + ((size_t)h << 20) + ((size_t)a0 << 10);
#pragma unroll
        for (int t = 0; t < 4; t++) {
            int b = tid + t * 256;
#pragma unroll
            for (int r = 0; r < 8; r++)
                __stcs(&aout[((size_t)r << 10) + b], probs[r][b] * inv[r]);
        }

        // V phase: thread (bg, d4), bg = tid>>2 in [0,64), d4 = tid&3
        int d4 = tid & 3;
        int bg = tid >> 2;
        float4 acc[8];
#pragma unroll
        for (int r = 0; r < 8; r++) acc[r] = make_float4(0.f, 0.f, 0.f, 0.f);
        const float4* Vh = (const float4*)(g_V + h * 16384);
#pragma unroll 4
        for (int t = 0; t < 16; t++) {
            int b = bg + t * 64;
            float4 v4 = Vh[b * 4 + d4];
#pragma unroll
            for (int r = 0; r < 8; r++) {
                float e = probs[r][b];
                acc[r].x += e * v4.x; acc[r].y += e * v4.y;
                acc[r].z += e * v4.z; acc[r].w += e * v4.w;
            }
        }
#pragma unroll
        for (int r = 0; r < 8; r++) {
#pragma unroll
            for (int o = 16; o >= 4; o >>= 1) {
                acc[r].x += __shfl_xor_sync(~0u, acc[r].x, o);
                acc[r].y += __shfl_xor_sync(~0u, acc[r].y, o);
                acc[r].z += __shfl_xor_sync(~0u, acc[r].z, o);
                acc[r].w += __shfl_xor_sync(~0u, acc[r].w, o);
            }
        }
        if (lane < 4) {
#pragma unroll
            for (int r = 0; r < 8; r++) part4[wid][r][d4] = acc[r];
        }
        __syncthreads();
        if (tid < 128) {
            int r = tid >> 4, d = tid & 15;
            int dq = d >> 2, cmp = d & 3;
            float s = 0.f;
#pragma unroll
            for (int w = 0; w < 8; w++) s += ((const float*)&part4[w][r][dq])[cmp];
            g_outpre[h * 16384 + (a0 + r) * D_HEAD + d] = s * ginv[r];
        }
    }
}

// ---------------------------------------------------------------------------
extern "C" void kernel_launch(void* const* d_in, const int* in_sizes, int n_in,
                              void* d_out, int out_size) {
    const float* x      = (const float*)d_in[0];
    const float* sign   = (const float*)d_in[1];
    const float* weight = (const float*)d_in[2];
    const float* Wq     = (const float*)d_in[3];
    const float* Wk     = (const float*)d_in[4];
    const float* Wv     = (const float*)d_in[5];
    const float* Wout   = (const float*)d_in[6];
    const float* Wpos   = (const float*)d_in[7];
    const float* bpos   = (const float*)d_in[8];
    const float* conv_w = (const float*)d_in[9];
    const float* conv_b = (const float*)d_in[10];
    const float* param  = (const float*)d_in[11];
    const int*   seq    = (const int*)d_in[12];
    const int*   ei     = (const int*)d_in[13];

    float* out  = (float*)d_out;              // [1024, 128]
    float* attn = out + N_NODES * C_DIM;      // [1, 8, 1024, 1024]

    const int P_SMEM = SEQ_MAX * C_DIM * (int)sizeof(__half);  // 128KB dynamic
    static bool attr_set = false;
    if (!attr_set) {
        cudaFuncSetAttribute(attn_kernel,
                             cudaFuncAttributeMaxDynamicSharedMemorySize, P_SMEM);
        attr_set = true;
    }

    zero_conv_kernel<<<NN / 4 / 256, 256>>>();
    scatter_conv_kernel<<<E_EDGES / 256, 256>>>(ei, sign, weight, conv_w);
    qkvp_gemm_kernel<<<dim3(16, 2, 4), 256>>>(x, Wq, Wk, Wv, Wpos, bpos);
    attn_kernel<<<ATTN_BLOCKS, 256, P_SMEM>>>(seq, param, conv_b, attn);
    out_gemm_kernel<<<dim3(16, 2), 256>>>(Wout, out);
}

// round 11
// speedup vs baseline: 1.2439x; 1.0226x over previous
#include <cuda_runtime.h>
#include <cuda_fp16.h>
#include <math.h>

#define N_NODES 1024
#define C_DIM   128
#define H_HEADS 8
#define D_HEAD  16
#define E_EDGES 32768
#define NN      (N_NODES * N_NODES)
#define SEQ_MAX 512
#define ATTN_BLOCKS 148

// Scratch (device globals; no allocation allowed)
__device__ float  g_conv[NN];               // fused conv output (scatter target)
__device__ float  g_Q[N_NODES * C_DIM];
__device__ float  g_K[N_NODES * C_DIM];
__device__ __half g_K16[N_NODES * C_DIM];   // fp16 K (rows = 32B)
__device__ float  g_V[N_NODES * C_DIM];
__device__ __half g_P16[SEQ_MAX * C_DIM];   // fp16 P table, rows rotated by (s%8) segments
__device__ float  g_WT[C_DIM * C_DIM];      // Wout transposed: WT[k][c] = Wout[c][k]

// ---------------------------------------------------------------------------
__global__ void zero_conv_kernel() {
    int i = blockIdx.x * blockDim.x + threadIdx.x;   // NN/4 float4s
    ((float4*)g_conv)[i] = make_float4(0.f, 0.f, 0.f, 0.f);
}

// Fused scatter + 1x1 conv: adjflat[f] with f = 3*(r*1024+c)+t contributes
// conv_w[f/NN] * val at conv position f % NN.
__global__ void scatter_conv_kernel(const int* __restrict__ ei,
                                    const float* __restrict__ sign,
                                    const float* __restrict__ w,
                                    const float* __restrict__ cw) {
    int e = blockIdx.x * blockDim.x + threadIdx.x;
    if (e >= E_EDGES) return;
    int r = ei[e];
    int c = ei[E_EDGES + e];
    float vals[3] = { sign[2 * e], sign[2 * e + 1], w[e] };
    unsigned f0 = 3u * ((unsigned)r * N_NODES + (unsigned)c);
#pragma unroll
    for (int t = 0; t < 3; t++) {
        unsigned f = f0 + t;
        atomicAdd(g_conv + (f & (NN - 1)), cw[f >> 20] * vals[t]);
    }
}

// ---------------------------------------------------------------------------
// SGEMM body: O[n, c] = (bias? bias[c] : 0) + sum_k A[n,k] * W[c,k]
// 64x64 block tile, 4x4 register tile, K=128 in two 64-chunks.
// isPE: A is the sinusoid table computed inline, output goes to g_P16 as
// fp16 with per-row rotation by (s%8) 16-half segments.
// toHalfK: additionally writes an fp16 copy to g_K16.
#define KPAD 68
__device__ __forceinline__ void gemm64_body(const float* __restrict__ A,
                                            const float* __restrict__ W,
                                            const float* __restrict__ bias,
                                            float* __restrict__ O,
                                            bool isPE, bool toHalfK) {
    __shared__ float As[64][KPAD];
    __shared__ float Ws[64][KPAD];
    int tid = threadIdx.x;
    int n0 = blockIdx.x * 64;
    int c0 = blockIdx.y * 64;
    int tx = tid & 15;
    int ty = tid >> 4;

    float acc[4][4];
#pragma unroll
    for (int i = 0; i < 4; i++)
#pragma unroll
        for (int j = 0; j < 4; j++)
            acc[i][j] = 0.f;

    int m = tid & 63;
    int kq0 = tid >> 6;          // 0..3

    for (int kc = 0; kc < 2; kc++) {
        int k0 = kc * 64;
#pragma unroll
        for (int j = 0; j < 4; j++) {
            int kq = kq0 + j * 4;                    // 0..15
            float4 wv = *(const float4*)(W + (size_t)(c0 + m) * C_DIM + k0 + kq * 4);
            Ws[kq * 4 + 0][m] = wv.x; Ws[kq * 4 + 1][m] = wv.y;
            Ws[kq * 4 + 2][m] = wv.z; Ws[kq * 4 + 3][m] = wv.w;
            if (!isPE) {
                float4 av = *(const float4*)(A + (size_t)(n0 + m) * C_DIM + k0 + kq * 4);
                As[kq * 4 + 0][m] = av.x; As[kq * 4 + 1][m] = av.y;
                As[kq * 4 + 2][m] = av.z; As[kq * 4 + 3][m] = av.w;
            } else {
                int s = n0 + m;
#pragma unroll
                for (int u = 0; u < 4; u++) {
                    int c = k0 + kq * 4 + u;
                    int jj = c & 63;
                    float invf = exp2f(-(float)jj * 0.2076205059280929f);
                    float arg = (float)s * invf;
                    As[kq * 4 + u][m] = (c < 64) ? sinf(arg) : cosf(arg);
                }
            }
        }
        __syncthreads();
#pragma unroll
        for (int k = 0; k < 64; k++) {
            float4 a4 = *(const float4*)&As[k][ty * 4];
            float4 b4 = *(const float4*)&Ws[k][tx * 4];
            float a[4] = { a4.x, a4.y, a4.z, a4.w };
            float b[4] = { b4.x, b4.y, b4.z, b4.w };
#pragma unroll
            for (int i = 0; i < 4; i++)
#pragma unroll
                for (int j = 0; j < 4; j++)
                    acc[i][j] += a[i] * b[j];
        }
        __syncthreads();
    }
#pragma unroll
    for (int i = 0; i < 4; i++) {
        float b0 = bias ? bias[c0 + tx * 4 + 0] : 0.f;
        float b1 = bias ? bias[c0 + tx * 4 + 1] : 0.f;
        float b2 = bias ? bias[c0 + tx * 4 + 2] : 0.f;
        float b3 = bias ? bias[c0 + tx * 4 + 3] : 0.f;
        float o0 = acc[i][0] + b0, o1 = acc[i][1] + b1;
        float o2 = acc[i][2] + b2, o3 = acc[i][3] + b3;
        if (!isPE) {
            size_t idx = (size_t)(n0 + ty * 4 + i) * C_DIM + c0 + tx * 4;
            *(float4*)(O + idx) = make_float4(o0, o1, o2, o3);
            if (toHalfK) {
                *(__half2*)(g_K16 + idx)     = __floats2half2_rn(o0, o1);
                *(__half2*)(g_K16 + idx + 2) = __floats2half2_rn(o2, o3);
            }
        } else {
            int s = n0 + ty * 4 + i;
            int cc = c0 + tx * 4;
            int ccr = (cc + ((s & 7) << 4)) & 127;   // rotate by (s%8) segments
            *(__half2*)(g_P16 + s * C_DIM + ccr)     = __floats2half2_rn(o0, o1);
            *(__half2*)(g_P16 + s * C_DIM + ccr + 2) = __floats2half2_rn(o2, o3);
        }
    }
}

// Merged: z=0..2 -> Q/K/V GEMMs; z=3 -> P-table GEMM (inline PE);
// z=4 -> Wout transpose into g_WT.
__global__ void qkvp_gemm_kernel(const float* __restrict__ x,
                                 const float* __restrict__ Wq,
                                 const float* __restrict__ Wk,
                                 const float* __restrict__ Wv,
                                 const float* __restrict__ Wpos,
                                 const float* __restrict__ bpos,
                                 const float* __restrict__ Wout) {
    int z = blockIdx.z;
    if (z == 4) {
        // transpose Wout (128x128): block (x,y) handles 4 rows c0..c0+3
        int c0 = (blockIdx.y * 16 + blockIdx.x) * 4;
        int tid = threadIdx.x;
#pragma unroll
        for (int j = 0; j < 2; j++) {
            int idx = tid + j * 256;        // 512 elements = 4 rows x 128
            int cc = c0 + (idx >> 7);
            int k = idx & 127;
            g_WT[k * C_DIM + cc] = Wout[cc * C_DIM + k];
        }
    } else if (z == 3) {
        if (blockIdx.x >= SEQ_MAX / 64) return;   // only 512 rows
        gemm64_body(nullptr, Wpos, bpos, nullptr, true, false);
    } else {
        const float* W = (z == 0) ? Wq : (z == 1) ? Wk : Wv;
        float* O = (z == 0) ? g_Q : (z == 1) ? g_K : g_V;
        gemm64_body(x, W, nullptr, O, false, z == 1);
    }
}

// ---------------------------------------------------------------------------
// Persistent attention: 148 blocks; each stages the fp16 P table into smem
// once, then loops over (h, ag) tiles. 256 threads. K read in fp16.
// Epilogue fuses the output projection: tile (h,ag) produces exactly row
// n = h*128+ag of outpre; out[n,:] = row @ Wout.T done in-block via g_WT.
__global__ void attn_kernel(const int* __restrict__ seq,
                            const float* __restrict__ param,
                            const float* __restrict__ conv_b,
                            float* __restrict__ attn_out,
                            float* __restrict__ out) {
    extern __shared__ __half smP[];     // 512*128 halves = 128KB, rotated rows

    int tid = threadIdx.x;
    int lane = tid & 31;
    int wid = tid >> 5;

    __shared__ float4 qs4[8][4];        // 8 q vectors (16 floats each)
    __shared__ int   srow[1024];        // seq row i
    __shared__ float probs[8][1024];    // 32KB: logits -> exp values
    __shared__ float wred[8][8];
    __shared__ float gmaxs[8];
    __shared__ float ginv[8];
    __shared__ float4 part4[8][8][4];   // [warp][r][d4]
    __shared__ float rowbuf[C_DIM];     // outpre row for this tile
    __shared__ float4 partmv[8][32];    // matvec partials [kh][c4]

    // Stage the whole P table once (coalesced float4 copy).
    {
        const float4* src = (const float4*)g_P16;   // 8192 float4s
        float4* dst = (float4*)smP;
#pragma unroll
        for (int j = 0; j < 32; j++)
            dst[tid + j * 256] = src[tid + j * 256];
    }

    const float LOG2E = 1.4426950408889634f;
    const float SCALE2 = 0.0883883476483184f * LOG2E;  // (1/sqrt(128))*log2(e)
    float prm2 = param[0] * LOG2E;
    float cb  = conv_b[0];

    for (int tile = blockIdx.x; tile < H_HEADS * 128; tile += ATTN_BLOCKS) {
        int h = tile >> 7;
        int ag = tile & 127;
        int a0 = ag * 8;

        __syncthreads();   // table staged (first iter) / prior tile fully done
        if (tid < 128) ((float*)qs4)[tid] = g_Q[h * 16384 + a0 * D_HEAD + tid];
        {
            int i = h * 128 + ag;
#pragma unroll
            for (int j = 0; j < 4; j++)
                srow[tid + j * 256] = seq[(size_t)i * N_NODES + tid + j * 256];
        }
        __syncthreads();

        float lmax[8];
#pragma unroll
        for (int r = 0; r < 8; r++) lmax[r] = -1e30f;

        const __half* K16h = g_K16 + h * 16384;
#pragma unroll
        for (int t = 0; t < 4; t++) {
            int b = tid + t * 256;
            // fp16 K row: 32B = 2x float4-of-halves
            float4 ka = *(const float4*)(K16h + b * 16);
            float4 kb = *(const float4*)(K16h + b * 16 + 8);
            const __half2* kA = (const __half2*)&ka;
            const __half2* kB = (const __half2*)&kb;
            float2 km0 = __half22float2(kA[0]);
            float2 km1 = __half22float2(kA[1]);
            float2 km2 = __half22float2(kA[2]);
            float2 km3 = __half22float2(kA[3]);
            float2 km4 = __half22float2(kB[0]);
            float2 km5 = __half22float2(kB[1]);
            float2 km6 = __half22float2(kB[2]);
            float2 km7 = __half22float2(kB[3]);
            int oct = b >> 3;
            int jj = b & 7;
#pragma unroll
            for (int r = 0; r < 8; r++) {
                int s = srow[r * 128 + oct];
                // rotated segment: physical start = ((jj + s) & 7) * 16 halves
                const __half* prow = smP + (s << 7) + (((jj + s) & 7) << 4);
                float4 ha = *(const float4*)(prow);        // halves 0..7
                float4 hb = *(const float4*)(prow + 8);    // halves 8..15
                const __half2* hA = (const __half2*)&ha;
                const __half2* hB = (const __half2*)&hb;
                float2 p0 = __half22float2(hA[0]);
                float2 p1 = __half22float2(hA[1]);
                float2 p2 = __half22float2(hA[2]);
                float2 p3 = __half22float2(hA[3]);
                float2 p4 = __half22float2(hB[0]);
                float2 p5 = __half22float2(hB[1]);
                float2 p6 = __half22float2(hB[2]);
                float2 p7 = __half22float2(hB[3]);
                float4 q0 = qs4[r][0], q1 = qs4[r][1], q2 = qs4[r][2], q3 = qs4[r][3];
                float cont = q0.x*km0.x + q0.y*km0.y + q0.z*km1.x + q0.w*km1.y
                           + q1.x*km2.x + q1.y*km2.y + q1.z*km3.x + q1.w*km3.y
                           + q2.x*km4.x + q2.y*km4.y + q2.z*km5.x + q2.w*km5.y
                           + q3.x*km6.x + q3.y*km6.y + q3.z*km7.x + q3.w*km7.y;
                float pos  = q0.x*p0.x + q0.y*p0.y + q0.z*p1.x + q0.w*p1.y
                           + q1.x*p2.x + q1.y*p2.y + q1.z*p3.x + q1.w*p3.y
                           + q2.x*p4.x + q2.y*p4.y + q2.z*p5.x + q2.w*p5.y
                           + q3.x*p6.x + q3.y*p6.y + q3.z*p7.x + q3.w*p7.y;
                float cv = g_conv[(size_t)(a0 + r) * N_NODES + b];
                float lg = (cont + pos) * SCALE2 + prm2 * (cv + cb);
                probs[r][b] = lg;
                lmax[r] = fmaxf(lmax[r], lg);
            }
        }
        // block max per r
#pragma unroll
        for (int r = 0; r < 8; r++) {
            float v = lmax[r];
#pragma unroll
            for (int o = 16; o > 0; o >>= 1) v = fmaxf(v, __shfl_xor_sync(~0u, v, o));
            if (lane == 0) wred[r][wid] = v;
        }
        __syncthreads();
        if (tid < 64) {
            int r = tid >> 3, k = tid & 7;
            float v = wred[r][k];
#pragma unroll
            for (int o = 4; o > 0; o >>= 1) v = fmaxf(v, __shfl_xor_sync(~0u, v, o));
            if (k == 0) gmaxs[r] = v;
        }
        __syncthreads();

        // exp2 + sum (log2e pre-absorbed into logits)
        float lsum[8];
#pragma unroll
        for (int r = 0; r < 8; r++) lsum[r] = 0.f;
#pragma unroll
        for (int t = 0; t < 4; t++) {
            int b = tid + t * 256;
#pragma unroll
            for (int r = 0; r < 8; r++) {
                float e = exp2f(probs[r][b] - gmaxs[r]);
                probs[r][b] = e;
                lsum[r] += e;
            }
        }
#pragma unroll
        for (int r = 0; r < 8; r++) {
            float v = lsum[r];
#pragma unroll
            for (int o = 16; o > 0; o >>= 1) v += __shfl_xor_sync(~0u, v, o);
            if (lane == 0) wred[r][wid] = v;
        }
        __syncthreads();
        if (tid < 64) {
            int r = tid >> 3, k = tid & 7;
            float v = wred[r][k];
#pragma unroll
            for (int o = 4; o > 0; o >>= 1) v += __shfl_xor_sync(~0u, v, o);
            if (k == 0) ginv[r] = 1.f / v;
        }
        __syncthreads();

        // write normalized attn rows with streaming stores (probs keeps e)
        float inv[8];
#pragma unroll
        for (int r = 0; r < 8; r++) inv[r] = ginv[r];
        float* aout = attn_out + ((size_t)h << 20) + ((size_t)a0 << 10);
#pragma unroll
        for (int t = 0; t < 4; t++) {
            int b = tid + t * 256;
#pragma unroll
            for (int r = 0; r < 8; r++)
                __stcs(&aout[((size_t)r << 10) + b], probs[r][b] * inv[r]);
        }

        // V phase: thread (bg, d4), bg = tid>>2 in [0,64), d4 = tid&3
        int d4 = tid & 3;
        int bg = tid >> 2;
        float4 acc[8];
#pragma unroll
        for (int r = 0; r < 8; r++) acc[r] = make_float4(0.f, 0.f, 0.f, 0.f);
        const float4* Vh = (const float4*)(g_V + h * 16384);
#pragma unroll 4
        for (int t = 0; t < 16; t++) {
            int b = bg + t * 64;
            float4 v4 = Vh[b * 4 + d4];
#pragma unroll
            for (int r = 0; r < 8; r++) {
                float e = probs[r][b];
                acc[r].x += e * v4.x; acc[r].y += e * v4.y;
                acc[r].z += e * v4.z; acc[r].w += e * v4.w;
            }
        }
#pragma unroll
        for (int r = 0; r < 8; r++) {
#pragma unroll
            for (int o = 16; o >= 4; o >>= 1) {
                acc[r].x += __shfl_xor_sync(~0u, acc[r].x, o);
                acc[r].y += __shfl_xor_sync(~0u, acc[r].y, o);
                acc[r].z += __shfl_xor_sync(~0u, acc[r].z, o);
                acc[r].w += __shfl_xor_sync(~0u, acc[r].w, o);
            }
        }
        if (lane < 4) {
#pragma unroll
            for (int r = 0; r < 8; r++) part4[wid][r][d4] = acc[r];
        }
        __syncthreads();
        if (tid < 128) {
            int r = tid >> 4, d = tid & 15;
            int dq = d >> 2, cmp = d & 3;
            float s = 0.f;
#pragma unroll
            for (int w = 0; w < 8; w++) s += ((const float*)&part4[w][r][dq])[cmp];
            rowbuf[r * D_HEAD + d] = s * ginv[r];
        }
        __syncthreads();

        // Fused out-projection: out[n, :] = rowbuf @ Wout.T via g_WT (WT[k][c]).
        // thread j: c4 = j&31 (float4 col group), kh = j>>5 (16-k slice)
        {
            int c4 = tid & 31;
            int kh = tid >> 5;
            float4 mv = make_float4(0.f, 0.f, 0.f, 0.f);
#pragma unroll
            for (int kk = 0; kk < 16; kk++) {
                int k = kh * 16 + kk;
                float rv = rowbuf[k];
                float4 w4 = *(const float4*)(g_WT + k * C_DIM + c4 * 4);
                mv.x += rv * w4.x; mv.y += rv * w4.y;
                mv.z += rv * w4.z; mv.w += rv * w4.w;
            }
            partmv[kh][c4] = mv;
        }
        __syncthreads();
        if (tid < 32) {
            float4 s4 = make_float4(0.f, 0.f, 0.f, 0.f);
#pragma unroll
            for (int kh = 0; kh < 8; kh++) {
                float4 p = partmv[kh][tid];
                s4.x += p.x; s4.y += p.y; s4.z += p.z; s4.w += p.w;
            }
            int n = h * 128 + ag;
            *(float4*)(out + (size_t)n * C_DIM + tid * 4) = s4;
        }
    }
}

// ---------------------------------------------------------------------------
extern "C" void kernel_launch(void* const* d_in, const int* in_sizes, int n_in,
                              void* d_out, int out_size) {
    const float* x      = (const float*)d_in[0];
    const float* sign   = (const float*)d_in[1];
    const float* weight = (const float*)d_in[2];
    const float* Wq     = (const float*)d_in[3];
    const float* Wk     = (const float*)d_in[4];
    const float* Wv     = (const float*)d_in[5];
    const float* Wout   = (const float*)d_in[6];
    const float* Wpos   = (const float*)d_in[7];
    const float* bpos   = (const float*)d_in[8];
    const float* conv_w = (const float*)d_in[9];
    const float* conv_b = (const float*)d_in[10];
    const float* param  = (const float*)d_in[11];
    const int*   seq    = (const int*)d_in[12];
    const int*   ei     = (const int*)d_in[13];

    float* out  = (float*)d_out;              // [1024, 128]
    float* attn = out + N_NODES * C_DIM;      // [1, 8, 1024, 1024]

    const int P_SMEM = SEQ_MAX * C_DIM * (int)sizeof(__half);  // 128KB dynamic
    static bool attr_set = false;
    if (!attr_set) {
        cudaFuncSetAttribute(attn_kernel,
                             cudaFuncAttributeMaxDynamicSharedMemorySize, P_SMEM);
        attr_set = true;
    }

    zero_conv_kernel<<<NN / 4 / 256, 256>>>();
    scatter_conv_kernel<<<E_EDGES / 256, 256>>>(ei, sign, weight, conv_w);
    qkvp_gemm_kernel<<<dim3(16, 2, 5), 256>>>(x, Wq, Wk, Wv, Wpos, bpos, Wout);
    attn_kernel<<<ATTN_BLOCKS, 256, P_SMEM>>>(seq, param, conv_b, attn, out);
}

// round 12
// speedup vs baseline: 1.3046x; 1.0488x over previous
#include <cuda_runtime.h>
#include <cuda_fp16.h>
#include <math.h>

#define N_NODES 1024
#define C_DIM   128
#define H_HEADS 8
#define D_HEAD  16
#define E_EDGES 32768
#define NN      (N_NODES * N_NODES)
#define SEQ_MAX 512
#define ATTN_BLOCKS 148

// Scratch (device globals; no allocation allowed)
__device__ float  g_conv[NN];               // fused conv output (scatter target)
__device__ float  g_Q[N_NODES * C_DIM];
__device__ __half g_Q16[N_NODES * C_DIM];   // fp16 Q
__device__ float  g_K[N_NODES * C_DIM];
__device__ __half g_K16[N_NODES * C_DIM];   // fp16 K (rows = 32B)
__device__ float  g_V[N_NODES * C_DIM];
__device__ __half g_P16[SEQ_MAX * C_DIM];   // fp16 P table, rows rotated by (s%8) segments
__device__ float  g_WT[C_DIM * C_DIM];      // Wout transposed: WT[k][c] = Wout[c][k]

// ---------------------------------------------------------------------------
__global__ void zero_conv_kernel() {
    int i = blockIdx.x * blockDim.x + threadIdx.x;   // NN/4 float4s
    ((float4*)g_conv)[i] = make_float4(0.f, 0.f, 0.f, 0.f);
}

// Fused scatter + 1x1 conv: adjflat[f] with f = 3*(r*1024+c)+t contributes
// conv_w[f/NN] * val at conv position f % NN.
__global__ void scatter_conv_kernel(const int* __restrict__ ei,
                                    const float* __restrict__ sign,
                                    const float* __restrict__ w,
                                    const float* __restrict__ cw) {
    int e = blockIdx.x * blockDim.x + threadIdx.x;
    if (e >= E_EDGES) return;
    int r = ei[e];
    int c = ei[E_EDGES + e];
    float vals[3] = { sign[2 * e], sign[2 * e + 1], w[e] };
    unsigned f0 = 3u * ((unsigned)r * N_NODES + (unsigned)c);
#pragma unroll
    for (int t = 0; t < 3; t++) {
        unsigned f = f0 + t;
        atomicAdd(g_conv + (f & (NN - 1)), cw[f >> 20] * vals[t]);
    }
}

// ---------------------------------------------------------------------------
// SGEMM body: O[n, c] = (bias? bias[c] : 0) + sum_k A[n,k] * W[c,k]
// 64x64 block tile, 4x4 register tile, K=128 in two 64-chunks.
// isPE: A is the sinusoid table computed inline, output goes to g_P16 as
// fp16 with per-row rotation by (s%8) 16-half segments.
// Hout: optional fp16 copy target (g_Q16 / g_K16).
#define KPAD 68
__device__ __forceinline__ void gemm64_body(const float* __restrict__ A,
                                            const float* __restrict__ W,
                                            const float* __restrict__ bias,
                                            float* __restrict__ O,
                                            bool isPE, __half* __restrict__ Hout) {
    __shared__ float As[64][KPAD];
    __shared__ float Ws[64][KPAD];
    int tid = threadIdx.x;
    int n0 = blockIdx.x * 64;
    int c0 = blockIdx.y * 64;
    int tx = tid & 15;
    int ty = tid >> 4;

    float acc[4][4];
#pragma unroll
    for (int i = 0; i < 4; i++)
#pragma unroll
        for (int j = 0; j < 4; j++)
            acc[i][j] = 0.f;

    int m = tid & 63;
    int kq0 = tid >> 6;          // 0..3

    for (int kc = 0; kc < 2; kc++) {
        int k0 = kc * 64;
#pragma unroll
        for (int j = 0; j < 4; j++) {
            int kq = kq0 + j * 4;                    // 0..15
            float4 wv = *(const float4*)(W + (size_t)(c0 + m) * C_DIM + k0 + kq * 4);
            Ws[kq * 4 + 0][m] = wv.x; Ws[kq * 4 + 1][m] = wv.y;
            Ws[kq * 4 + 2][m] = wv.z; Ws[kq * 4 + 3][m] = wv.w;
            if (!isPE) {
                float4 av = *(const float4*)(A + (size_t)(n0 + m) * C_DIM + k0 + kq * 4);
                As[kq * 4 + 0][m] = av.x; As[kq * 4 + 1][m] = av.y;
                As[kq * 4 + 2][m] = av.z; As[kq * 4 + 3][m] = av.w;
            } else {
                int s = n0 + m;
#pragma unroll
                for (int u = 0; u < 4; u++) {
                    int c = k0 + kq * 4 + u;
                    int jj = c & 63;
                    float invf = exp2f(-(float)jj * 0.2076205059280929f);
                    float arg = (float)s * invf;
                    As[kq * 4 + u][m] = (c < 64) ? sinf(arg) : cosf(arg);
                }
            }
        }
        __syncthreads();
#pragma unroll
        for (int k = 0; k < 64; k++) {
            float4 a4 = *(const float4*)&As[k][ty * 4];
            float4 b4 = *(const float4*)&Ws[k][tx * 4];
            float a[4] = { a4.x, a4.y, a4.z, a4.w };
            float b[4] = { b4.x, b4.y, b4.z, b4.w };
#pragma unroll
            for (int i = 0; i < 4; i++)
#pragma unroll
                for (int j = 0; j < 4; j++)
                    acc[i][j] += a[i] * b[j];
        }
        __syncthreads();
    }
#pragma unroll
    for (int i = 0; i < 4; i++) {
        float b0 = bias ? bias[c0 + tx * 4 + 0] : 0.f;
        float b1 = bias ? bias[c0 + tx * 4 + 1] : 0.f;
        float b2 = bias ? bias[c0 + tx * 4 + 2] : 0.f;
        float b3 = bias ? bias[c0 + tx * 4 + 3] : 0.f;
        float o0 = acc[i][0] + b0, o1 = acc[i][1] + b1;
        float o2 = acc[i][2] + b2, o3 = acc[i][3] + b3;
        if (!isPE) {
            size_t idx = (size_t)(n0 + ty * 4 + i) * C_DIM + c0 + tx * 4;
            *(float4*)(O + idx) = make_float4(o0, o1, o2, o3);
            if (Hout) {
                *(__half2*)(Hout + idx)     = __floats2half2_rn(o0, o1);
                *(__half2*)(Hout + idx + 2) = __floats2half2_rn(o2, o3);
            }
        } else {
            int s = n0 + ty * 4 + i;
            int cc = c0 + tx * 4;
            int ccr = (cc + ((s & 7) << 4)) & 127;   // rotate by (s%8) segments
            *(__half2*)(g_P16 + s * C_DIM + ccr)     = __floats2half2_rn(o0, o1);
            *(__half2*)(g_P16 + s * C_DIM + ccr + 2) = __floats2half2_rn(o2, o3);
        }
    }
}

// Merged: z=0..2 -> Q/K/V GEMMs; z=3 -> P-table GEMM (inline PE);
// z=4 -> Wout transpose into g_WT.
__global__ void qkvp_gemm_kernel(const float* __restrict__ x,
                                 const float* __restrict__ Wq,
                                 const float* __restrict__ Wk,
                                 const float* __restrict__ Wv,
                                 const float* __restrict__ Wpos,
                                 const float* __restrict__ bpos,
                                 const float* __restrict__ Wout) {
    int z = blockIdx.z;
    if (z == 4) {
        // transpose Wout (128x128): block (x,y) handles 4 rows c0..c0+3
        int c0 = (blockIdx.y * 16 + blockIdx.x) * 4;
        int tid = threadIdx.x;
#pragma unroll
        for (int j = 0; j < 2; j++) {
            int idx = tid + j * 256;        // 512 elements = 4 rows x 128
            int cc = c0 + (idx >> 7);
            int k = idx & 127;
            g_WT[k * C_DIM + cc] = Wout[cc * C_DIM + k];
        }
    } else if (z == 3) {
        if (blockIdx.x >= SEQ_MAX / 64) return;   // only 512 rows
        gemm64_body(nullptr, Wpos, bpos, nullptr, true, nullptr);
    } else {
        const float* W = (z == 0) ? Wq : (z == 1) ? Wk : Wv;
        float* O = (z == 0) ? g_Q : (z == 1) ? g_K : g_V;
        __half* H = (z == 0) ? g_Q16 : (z == 1) ? g_K16 : nullptr;
        gemm64_body(x, W, nullptr, O, false, H);
    }
}

// ---------------------------------------------------------------------------
// Persistent attention: 148 blocks; each stages the fp16 P table into smem
// once, then loops over (h, ag) tiles. 256 threads. Q/K/P in fp16; dot
// products in HFMA2 (4 half2 accumulators), converted to fp32 per logit.
__global__ void attn_kernel(const int* __restrict__ seq,
                            const float* __restrict__ param,
                            const float* __restrict__ conv_b,
                            float* __restrict__ attn_out,
                            float* __restrict__ out) {
    extern __shared__ __half smP[];     // 512*128 halves = 128KB, rotated rows

    int tid = threadIdx.x;
    int lane = tid & 31;
    int wid = tid >> 5;

    __shared__ __half2 qs2[8][8];       // 8 q vectors (16 halves each)
    __shared__ int   srow[1024];        // seq row i
    __shared__ float probs[8][1024];    // 32KB: logits -> exp values
    __shared__ float wred[8][8];
    __shared__ float gmaxs[8];
    __shared__ float ginv[8];
    __shared__ float4 part4[8][8][4];   // [warp][r][d4]
    __shared__ float rowbuf[C_DIM];     // outpre row for this tile
    __shared__ float4 partmv[8][32];    // matvec partials [kh][c4]

    // Stage the whole P table once (coalesced float4 copy).
    {
        const float4* src = (const float4*)g_P16;   // 8192 float4s
        float4* dst = (float4*)smP;
#pragma unroll
        for (int j = 0; j < 32; j++)
            dst[tid + j * 256] = src[tid + j * 256];
    }

    const float LOG2E = 1.4426950408889634f;
    const float SCALE2 = 0.0883883476483184f * LOG2E;  // (1/sqrt(128))*log2(e)
    float prm2 = param[0] * LOG2E;
    float cb  = conv_b[0];

    for (int tile = blockIdx.x; tile < H_HEADS * 128; tile += ATTN_BLOCKS) {
        int h = tile >> 7;
        int ag = tile & 127;
        int a0 = ag * 8;

        __syncthreads();   // table staged (first iter) / prior tile fully done
        if (tid < 16) ((float4*)qs2)[tid] =
            ((const float4*)(g_Q16 + h * 16384 + a0 * D_HEAD))[tid];
        {
            int i = h * 128 + ag;
#pragma unroll
            for (int j = 0; j < 4; j++)
                srow[tid + j * 256] = seq[(size_t)i * N_NODES + tid + j * 256];
        }
        __syncthreads();

        float lmax[8];
#pragma unroll
        for (int r = 0; r < 8; r++) lmax[r] = -1e30f;

        const __half* K16h = g_K16 + h * 16384;
#pragma unroll
        for (int t = 0; t < 4; t++) {
            int b = tid + t * 256;
            // fp16 K row: 32B = 2x float4-of-halves (keep as half2, no cvt)
            float4 ka = *(const float4*)(K16h + b * 16);
            float4 kb = *(const float4*)(K16h + b * 16 + 8);
            __half2 k2[8];
            *(float4*)&k2[0] = ka;
            *(float4*)&k2[4] = kb;
            int oct = b >> 3;
            int jj = b & 7;
#pragma unroll
            for (int r = 0; r < 8; r++) {
                int s = srow[r * 128 + oct];
                // rotated segment: physical start = ((jj + s) & 7) * 16 halves
                const __half* prow = smP + (s << 7) + (((jj + s) & 7) << 4);
                __half2 p2[8];
                *(float4*)&p2[0] = *(const float4*)(prow);
                *(float4*)&p2[4] = *(const float4*)(prow + 8);
                float4 qa = *(const float4*)&qs2[r][0];
                float4 qb = *(const float4*)&qs2[r][4];
                __half2 q2[8];
                *(float4*)&q2[0] = qa;
                *(float4*)&q2[4] = qb;
                // cont+pos together: 4 half2 accumulators, 4 products each
                __half2 a0h = __hmul2(q2[0], k2[0]);
                __half2 a1h = __hmul2(q2[1], k2[1]);
                __half2 a2h = __hmul2(q2[2], k2[2]);
                __half2 a3h = __hmul2(q2[3], k2[3]);
                a0h = __hfma2(q2[4], k2[4], a0h);
                a1h = __hfma2(q2[5], k2[5], a1h);
                a2h = __hfma2(q2[6], k2[6], a2h);
                a3h = __hfma2(q2[7], k2[7], a3h);
                a0h = __hfma2(q2[0], p2[0], a0h);
                a1h = __hfma2(q2[1], p2[1], a1h);
                a2h = __hfma2(q2[2], p2[2], a2h);
                a3h = __hfma2(q2[3], p2[3], a3h);
                a0h = __hfma2(q2[4], p2[4], a0h);
                a1h = __hfma2(q2[5], p2[5], a1h);
                a2h = __hfma2(q2[6], p2[6], a2h);
                a3h = __hfma2(q2[7], p2[7], a3h);
                float2 f0 = __half22float2(a0h);
                float2 f1 = __half22float2(a1h);
                float2 f2 = __half22float2(a2h);
                float2 f3 = __half22float2(a3h);
                float dot = (f0.x + f0.y) + (f1.x + f1.y)
                          + (f2.x + f2.y) + (f3.x + f3.y);
                float cv = g_conv[(size_t)(a0 + r) * N_NODES + b];
                float lg = dot * SCALE2 + prm2 * (cv + cb);
                probs[r][b] = lg;
                lmax[r] = fmaxf(lmax[r], lg);
            }
        }
        // block max per r
#pragma unroll
        for (int r = 0; r < 8; r++) {
            float v = lmax[r];
#pragma unroll
            for (int o = 16; o > 0; o >>= 1) v = fmaxf(v, __shfl_xor_sync(~0u, v, o));
            if (lane == 0) wred[r][wid] = v;
        }
        __syncthreads();
        if (tid < 64) {
            int r = tid >> 3, k = tid & 7;
            float v = wred[r][k];
#pragma unroll
            for (int o = 4; o > 0; o >>= 1) v = fmaxf(v, __shfl_xor_sync(~0u, v, o));
            if (k == 0) gmaxs[r] = v;
        }
        __syncthreads();

        // exp2 + sum (log2e pre-absorbed into logits)
        float lsum[8];
#pragma unroll
        for (int r = 0; r < 8; r++) lsum[r] = 0.f;
#pragma unroll
        for (int t = 0; t < 4; t++) {
            int b = tid + t * 256;
#pragma unroll
            for (int r = 0; r < 8; r++) {
                float e = exp2f(probs[r][b] - gmaxs[r]);
                probs[r][b] = e;
                lsum[r] += e;
            }
        }
#pragma unroll
        for (int r = 0; r < 8; r++) {
            float v = lsum[r];
#pragma unroll
            for (int o = 16; o > 0; o >>= 1) v += __shfl_xor_sync(~0u, v, o);
            if (lane == 0) wred[r][wid] = v;
        }
        __syncthreads();
        if (tid < 64) {
            int r = tid >> 3, k = tid & 7;
            float v = wred[r][k];
#pragma unroll
            for (int o = 4; o > 0; o >>= 1) v += __shfl_xor_sync(~0u, v, o);
            if (k == 0) ginv[r] = 1.f / v;
        }
        __syncthreads();

        // write normalized attn rows with streaming stores (probs keeps e)
        float inv[8];
#pragma unroll
        for (int r = 0; r < 8; r++) inv[r] = ginv[r];
        float* aout = attn_out + ((size_t)h << 20) + ((size_t)a0 << 10);
#pragma unroll
        for (int t = 0; t < 4; t++) {
            int b = tid + t * 256;
#pragma unroll
            for (int r = 0; r < 8; r++)
                __stcs(&aout[((size_t)r << 10) + b], probs[r][b] * inv[r]);
        }

        // V phase: thread (bg, d4), bg = tid>>2 in [0,64), d4 = tid&3
        int d4 = tid & 3;
        int bg = tid >> 2;
        float4 acc[8];
#pragma unroll
        for (int r = 0; r < 8; r++) acc[r] = make_float4(0.f, 0.f, 0.f, 0.f);
        const float4* Vh = (const float4*)(g_V + h * 16384);
#pragma unroll 4
        for (int t = 0; t < 16; t++) {
            int b = bg + t * 64;
            float4 v4 = Vh[b * 4 + d4];
#pragma unroll
            for (int r = 0; r < 8; r++) {
                float e = probs[r][b];
                acc[r].x += e * v4.x; acc[r].y += e * v4.y;
                acc[r].z += e * v4.z; acc[r].w += e * v4.w;
            }
        }
#pragma unroll
        for (int r = 0; r < 8; r++) {
#pragma unroll
            for (int o = 16; o >= 4; o >>= 1) {
                acc[r].x += __shfl_xor_sync(~0u, acc[r].x, o);
                acc[r].y += __shfl_xor_sync(~0u, acc[r].y, o);
                acc[r].z += __shfl_xor_sync(~0u, acc[r].z, o);
                acc[r].w += __shfl_xor_sync(~0u, acc[r].w, o);
            }
        }
        if (lane < 4) {
#pragma unroll
            for (int r = 0; r < 8; r++) part4[wid][r][d4] = acc[r];
        }
        __syncthreads();
        if (tid < 128) {
            int r = tid >> 4, d = tid & 15;
            int dq = d >> 2, cmp = d & 3;
            float s = 0.f;
#pragma unroll
            for (int w = 0; w < 8; w++) s += ((const float*)&part4[w][r][dq])[cmp];
            rowbuf[r * D_HEAD + d] = s * ginv[r];
        }
        __syncthreads();

        // Fused out-projection: out[n, :] = rowbuf @ Wout.T via g_WT (WT[k][c]).
        {
            int c4 = tid & 31;
            int kh = tid >> 5;
            float4 mv = make_float4(0.f, 0.f, 0.f, 0.f);
#pragma unroll
            for (int kk = 0; kk < 16; kk++) {
                int k = kh * 16 + kk;
                float rv = rowbuf[k];
                float4 w4 = *(const float4*)(g_WT + k * C_DIM + c4 * 4);
                mv.x += rv * w4.x; mv.y += rv * w4.y;
                mv.z += rv * w4.z; mv.w += rv * w4.w;
            }
            partmv[kh][c4] = mv;
        }
        __syncthreads();
        if (tid < 32) {
            float4 s4 = make_float4(0.f, 0.f, 0.f, 0.f);
#pragma unroll
            for (int kh = 0; kh < 8; kh++) {
                float4 p = partmv[kh][tid];
                s4.x += p.x; s4.y += p.y; s4.z += p.z; s4.w += p.w;
            }
            int n = h * 128 + ag;
            *(float4*)(out + (size_t)n * C_DIM + tid * 4) = s4;
        }
    }
}

// ---------------------------------------------------------------------------
extern "C" void kernel_launch(void* const* d_in, const int* in_sizes, int n_in,
                              void* d_out, int out_size) {
    const float* x      = (const float*)d_in[0];
    const float* sign   = (const float*)d_in[1];
    const float* weight = (const float*)d_in[2];
    const float* Wq     = (const float*)d_in[3];
    const float* Wk     = (const float*)d_in[4];
    const float* Wv     = (const float*)d_in[5];
    const float* Wout   = (const float*)d_in[6];
    const float* Wpos   = (const float*)d_in[7];
    const float* bpos   = (const float*)d_in[8];
    const float* conv_w = (const float*)d_in[9];
    const float* conv_b = (const float*)d_in[10];
    const float* param  = (const float*)d_in[11];
    const int*   seq    = (const int*)d_in[12];
    const int*   ei     = (const int*)d_in[13];

    float* out  = (float*)d_out;              // [1024, 128]
    float* attn = out + N_NODES * C_DIM;      // [1, 8, 1024, 1024]

    const int P_SMEM = SEQ_MAX * C_DIM * (int)sizeof(__half);  // 128KB dynamic
    static bool attr_set = false;
    if (!attr_set) {
        cudaFuncSetAttribute(attn_kernel,
                             cudaFuncAttributeMaxDynamicSharedMemorySize, P_SMEM);
        attr_set = true;
    }

    zero_conv_kernel<<<NN / 4 / 256, 256>>>();
    scatter_conv_kernel<<<E_EDGES / 256, 256>>>(ei, sign, weight, conv_w);
    qkvp_gemm_kernel<<<dim3(16, 2, 5), 256>>>(x, Wq, Wk, Wv, Wpos, bpos, Wout);
    attn_kernel<<<ATTN_BLOCKS, 256, P_SMEM>>>(seq, param, conv_b, attn, out);
}

// round 13
// speedup vs baseline: 1.3977x; 1.0713x over previous
#include <cuda_runtime.h>
#include <cuda_fp16.h>
#include <math.h>

#define N_NODES 1024
#define C_DIM   128
#define H_HEADS 8
#define D_HEAD  16
#define E_EDGES 32768
#define NN      (N_NODES * N_NODES)
#define SEQ_MAX 512
#define ATTN_BLOCKS 148

// Scratch (device globals; no allocation allowed)
__device__ float  g_conv[NN];               // fused conv output (scatter target)
__device__ float  g_Q[N_NODES * C_DIM];
__device__ __half g_Q16[N_NODES * C_DIM];   // fp16 Q
__device__ float  g_K[N_NODES * C_DIM];
__device__ __half g_K16[N_NODES * C_DIM];   // fp16 K (rows = 32B)
__device__ float  g_V[N_NODES * C_DIM];
__device__ __half g_V16[N_NODES * C_DIM];   // fp16 V (rows = 32B)
__device__ __half g_P16[SEQ_MAX * C_DIM];   // fp16 P table, rows rotated by (s%8) segments
__device__ float  g_WT[C_DIM * C_DIM];      // Wout transposed: WT[k][c] = Wout[c][k]

// ---------------------------------------------------------------------------
__global__ void zero_conv_kernel() {
    int i = blockIdx.x * blockDim.x + threadIdx.x;   // NN/4 float4s
    ((float4*)g_conv)[i] = make_float4(0.f, 0.f, 0.f, 0.f);
}

// Fused scatter + 1x1 conv: adjflat[f] with f = 3*(r*1024+c)+t contributes
// conv_w[f/NN] * val at conv position f % NN.
__global__ void scatter_conv_kernel(const int* __restrict__ ei,
                                    const float* __restrict__ sign,
                                    const float* __restrict__ w,
                                    const float* __restrict__ cw) {
    int e = blockIdx.x * blockDim.x + threadIdx.x;
    if (e >= E_EDGES) return;
    int r = ei[e];
    int c = ei[E_EDGES + e];
    float vals[3] = { sign[2 * e], sign[2 * e + 1], w[e] };
    unsigned f0 = 3u * ((unsigned)r * N_NODES + (unsigned)c);
#pragma unroll
    for (int t = 0; t < 3; t++) {
        unsigned f = f0 + t;
        atomicAdd(g_conv + (f & (NN - 1)), cw[f >> 20] * vals[t]);
    }
}

// ---------------------------------------------------------------------------
// SGEMM body: O[n, c] = (bias? bias[c] : 0) + sum_k A[n,k] * W[c,k]
// 64x64 block tile, 4x4 register tile, K=128 in two 64-chunks.
// isPE: A is the sinusoid table computed inline, output goes to g_P16 as
// fp16 with per-row rotation by (s%8) 16-half segments.
// Hout: optional fp16 copy target (g_Q16 / g_K16 / g_V16).
#define KPAD 68
__device__ __forceinline__ void gemm64_body(const float* __restrict__ A,
                                            const float* __restrict__ W,
                                            const float* __restrict__ bias,
                                            float* __restrict__ O,
                                            bool isPE, __half* __restrict__ Hout) {
    __shared__ float As[64][KPAD];
    __shared__ float Ws[64][KPAD];
    int tid = threadIdx.x;
    int n0 = blockIdx.x * 64;
    int c0 = blockIdx.y * 64;
    int tx = tid & 15;
    int ty = tid >> 4;

    float acc[4][4];
#pragma unroll
    for (int i = 0; i < 4; i++)
#pragma unroll
        for (int j = 0; j < 4; j++)
            acc[i][j] = 0.f;

    int m = tid & 63;
    int kq0 = tid >> 6;          // 0..3

    for (int kc = 0; kc < 2; kc++) {
        int k0 = kc * 64;
#pragma unroll
        for (int j = 0; j < 4; j++) {
            int kq = kq0 + j * 4;                    // 0..15
            float4 wv = *(const float4*)(W + (size_t)(c0 + m) * C_DIM + k0 + kq * 4);
            Ws[kq * 4 + 0][m] = wv.x; Ws[kq * 4 + 1][m] = wv.y;
            Ws[kq * 4 + 2][m] = wv.z; Ws[kq * 4 + 3][m] = wv.w;
            if (!isPE) {
                float4 av = *(const float4*)(A + (size_t)(n0 + m) * C_DIM + k0 + kq * 4);
                As[kq * 4 + 0][m] = av.x; As[kq * 4 + 1][m] = av.y;
                As[kq * 4 + 2][m] = av.z; As[kq * 4 + 3][m] = av.w;
            } else {
                int s = n0 + m;
#pragma unroll
                for (int u = 0; u < 4; u++) {
                    int c = k0 + kq * 4 + u;
                    int jj = c & 63;
                    float invf = exp2f(-(float)jj * 0.2076205059280929f);
                    float arg = (float)s * invf;
                    As[kq * 4 + u][m] = (c < 64) ? sinf(arg) : cosf(arg);
                }
            }
        }
        __syncthreads();
#pragma unroll
        for (int k = 0; k < 64; k++) {
            float4 a4 = *(const float4*)&As[k][ty * 4];
            float4 b4 = *(const float4*)&Ws[k][tx * 4];
            float a[4] = { a4.x, a4.y, a4.z, a4.w };
            float b[4] = { b4.x, b4.y, b4.z, b4.w };
#pragma unroll
            for (int i = 0; i < 4; i++)
#pragma unroll
                for (int j = 0; j < 4; j++)
                    acc[i][j] += a[i] * b[j];
        }
        __syncthreads();
    }
#pragma unroll
    for (int i = 0; i < 4; i++) {
        float b0 = bias ? bias[c0 + tx * 4 + 0] : 0.f;
        float b1 = bias ? bias[c0 + tx * 4 + 1] : 0.f;
        float b2 = bias ? bias[c0 + tx * 4 + 2] : 0.f;
        float b3 = bias ? bias[c0 + tx * 4 + 3] : 0.f;
        float o0 = acc[i][0] + b0, o1 = acc[i][1] + b1;
        float o2 = acc[i][2] + b2, o3 = acc[i][3] + b3;
        if (!isPE) {
            size_t idx = (size_t)(n0 + ty * 4 + i) * C_DIM + c0 + tx * 4;
            *(float4*)(O + idx) = make_float4(o0, o1, o2, o3);
            if (Hout) {
                *(__half2*)(Hout + idx)     = __floats2half2_rn(o0, o1);
                *(__half2*)(Hout + idx + 2) = __floats2half2_rn(o2, o3);
            }
        } else {
            int s = n0 + ty * 4 + i;
            int cc = c0 + tx * 4;
            int ccr = (cc + ((s & 7) << 4)) & 127;   // rotate by (s%8) segments
            *(__half2*)(g_P16 + s * C_DIM + ccr)     = __floats2half2_rn(o0, o1);
            *(__half2*)(g_P16 + s * C_DIM + ccr + 2) = __floats2half2_rn(o2, o3);
        }
    }
}

// Merged: z=0..2 -> Q/K/V GEMMs; z=3 -> P-table GEMM (inline PE);
// z=4 -> Wout transpose into g_WT.
__global__ void qkvp_gemm_kernel(const float* __restrict__ x,
                                 const float* __restrict__ Wq,
                                 const float* __restrict__ Wk,
                                 const float* __restrict__ Wv,
                                 const float* __restrict__ Wpos,
                                 const float* __restrict__ bpos,
                                 const float* __restrict__ Wout) {
    int z = blockIdx.z;
    if (z == 4) {
        // transpose Wout (128x128): block (x,y) handles 4 rows c0..c0+3
        int c0 = (blockIdx.y * 16 + blockIdx.x) * 4;
        int tid = threadIdx.x;
#pragma unroll
        for (int j = 0; j < 2; j++) {
            int idx = tid + j * 256;        // 512 elements = 4 rows x 128
            int cc = c0 + (idx >> 7);
            int k = idx & 127;
            g_WT[k * C_DIM + cc] = Wout[cc * C_DIM + k];
        }
    } else if (z == 3) {
        if (blockIdx.x >= SEQ_MAX / 64) return;   // only 512 rows
        gemm64_body(nullptr, Wpos, bpos, nullptr, true, nullptr);
    } else {
        const float* W = (z == 0) ? Wq : (z == 1) ? Wk : Wv;
        float* O = (z == 0) ? g_Q : (z == 1) ? g_K : g_V;
        __half* H = (z == 0) ? g_Q16 : (z == 1) ? g_K16 : g_V16;
        gemm64_body(x, W, nullptr, O, false, H);
    }
}

// ---------------------------------------------------------------------------
// Persistent attention: 148 blocks; each stages the fp16 P table into smem
// once, then loops over (h, ag) tiles. 256 threads. Q/K/P/V in fp16.
// Logits live in registers (smem occupancy-bound -> regs are free); probs
// smem is written ONCE (for the V phase's different mapping) and read ONCE.
__global__ void attn_kernel(const int* __restrict__ seq,
                            const float* __restrict__ param,
                            const float* __restrict__ conv_b,
                            float* __restrict__ attn_out,
                            float* __restrict__ out) {
    extern __shared__ __half smP[];     // 512*128 halves = 128KB, rotated rows

    int tid = threadIdx.x;
    int lane = tid & 31;
    int wid = tid >> 5;

    __shared__ __half2 qs2[8][8];       // 8 q vectors (16 halves each)
    __shared__ int   srow[1024];        // seq row i
    __shared__ float probs[8][1024];    // 32KB: exp values (written once)
    __shared__ float wred[8][8];
    __shared__ float gmaxs[8];
    __shared__ float ginv[8];
    __shared__ float4 part4[8][8][4];   // [warp][r][d4]
    __shared__ float rowbuf[C_DIM];     // outpre row for this tile
    __shared__ float4 partmv[8][32];    // matvec partials [kh][c4]

    // Stage the whole P table once (coalesced float4 copy).
    {
        const float4* src = (const float4*)g_P16;   // 8192 float4s
        float4* dst = (float4*)smP;
#pragma unroll
        for (int j = 0; j < 32; j++)
            dst[tid + j * 256] = src[tid + j * 256];
    }

    const float LOG2E = 1.4426950408889634f;
    const float SCALE2 = 0.0883883476483184f * LOG2E;  // (1/sqrt(128))*log2(e)
    float prm2 = param[0] * LOG2E;
    float cb  = conv_b[0];

    for (int tile = blockIdx.x; tile < H_HEADS * 128; tile += ATTN_BLOCKS) {
        int h = tile >> 7;
        int ag = tile & 127;
        int a0 = ag * 8;

        __syncthreads();   // table staged (first iter) / prior tile fully done
        if (tid < 16) ((float4*)qs2)[tid] =
            ((const float4*)(g_Q16 + h * 16384 + a0 * D_HEAD))[tid];
        {
            int i = h * 128 + ag;
#pragma unroll
            for (int j = 0; j < 4; j++)
                srow[tid + j * 256] = seq[(size_t)i * N_NODES + tid + j * 256];
        }
        __syncthreads();

        float lv[4][8];                 // logits in registers
        float lmax[8];
#pragma unroll
        for (int r = 0; r < 8; r++) lmax[r] = -1e30f;

        const __half* K16h = g_K16 + h * 16384;
#pragma unroll
        for (int t = 0; t < 4; t++) {
            int b = tid + t * 256;
            // fp16 K row: 32B = 2x float4-of-halves (keep as half2, no cvt)
            float4 ka = *(const float4*)(K16h + b * 16);
            float4 kb = *(const float4*)(K16h + b * 16 + 8);
            __half2 k2[8];
            *(float4*)&k2[0] = ka;
            *(float4*)&k2[4] = kb;
            int oct = b >> 3;
            int jj = b & 7;
#pragma unroll
            for (int r = 0; r < 8; r++) {
                int s = srow[r * 128 + oct];
                // rotated segment: physical start = ((jj + s) & 7) * 16 halves
                const __half* prow = smP + (s << 7) + (((jj + s) & 7) << 4);
                __half2 p2[8];
                *(float4*)&p2[0] = *(const float4*)(prow);
                *(float4*)&p2[4] = *(const float4*)(prow + 8);
                float4 qa = *(const float4*)&qs2[r][0];
                float4 qb = *(const float4*)&qs2[r][4];
                __half2 q2[8];
                *(float4*)&q2[0] = qa;
                *(float4*)&q2[4] = qb;
                // cont+pos together: 4 half2 accumulators, 4 products each
                __half2 a0h = __hmul2(q2[0], k2[0]);
                __half2 a1h = __hmul2(q2[1], k2[1]);
                __half2 a2h = __hmul2(q2[2], k2[2]);
                __half2 a3h = __hmul2(q2[3], k2[3]);
                a0h = __hfma2(q2[4], k2[4], a0h);
                a1h = __hfma2(q2[5], k2[5], a1h);
                a2h = __hfma2(q2[6], k2[6], a2h);
                a3h = __hfma2(q2[7], k2[7], a3h);
                a0h = __hfma2(q2[0], p2[0], a0h);
                a1h = __hfma2(q2[1], p2[1], a1h);
                a2h = __hfma2(q2[2], p2[2], a2h);
                a3h = __hfma2(q2[3], p2[3], a3h);
                a0h = __hfma2(q2[4], p2[4], a0h);
                a1h = __hfma2(q2[5], p2[5], a1h);
                a2h = __hfma2(q2[6], p2[6], a2h);
                a3h = __hfma2(q2[7], p2[7], a3h);
                float2 f0 = __half22float2(a0h);
                float2 f1 = __half22float2(a1h);
                float2 f2 = __half22float2(a2h);
                float2 f3 = __half22float2(a3h);
                float dot = (f0.x + f0.y) + (f1.x + f1.y)
                          + (f2.x + f2.y) + (f3.x + f3.y);
                float cv = g_conv[(size_t)(a0 + r) * N_NODES + b];
                float lg = dot * SCALE2 + prm2 * (cv + cb);
                lv[t][r] = lg;
                lmax[r] = fmaxf(lmax[r], lg);
            }
        }
        // block max per r
#pragma unroll
        for (int r = 0; r < 8; r++) {
            float v = lmax[r];
#pragma unroll
            for (int o = 16; o > 0; o >>= 1) v = fmaxf(v, __shfl_xor_sync(~0u, v, o));
            if (lane == 0) wred[r][wid] = v;
        }
        __syncthreads();
        if (tid < 64) {
            int r = tid >> 3, k = tid & 7;
            float v = wred[r][k];
#pragma unroll
            for (int o = 4; o > 0; o >>= 1) v = fmaxf(v, __shfl_xor_sync(~0u, v, o));
            if (k == 0) gmaxs[r] = v;
        }
        __syncthreads();

        // exp2 in registers; single STS into probs (for V phase)
        float lsum[8];
#pragma unroll
        for (int r = 0; r < 8; r++) lsum[r] = 0.f;
#pragma unroll
        for (int t = 0; t < 4; t++) {
            int b = tid + t * 256;
#pragma unroll
            for (int r = 0; r < 8; r++) {
                float e = exp2f(lv[t][r] - gmaxs[r]);
                lv[t][r] = e;
                probs[r][b] = e;
                lsum[r] += e;
            }
        }
#pragma unroll
        for (int r = 0; r < 8; r++) {
            float v = lsum[r];
#pragma unroll
            for (int o = 16; o > 0; o >>= 1) v += __shfl_xor_sync(~0u, v, o);
            if (lane == 0) wred[r][wid] = v;
        }
        __syncthreads();
        if (tid < 64) {
            int r = tid >> 3, k = tid & 7;
            float v = wred[r][k];
#pragma unroll
            for (int o = 4; o > 0; o >>= 1) v += __shfl_xor_sync(~0u, v, o);
            if (k == 0) ginv[r] = 1.f / v;
        }
        __syncthreads();

        // write normalized attn rows directly from registers (streaming)
        float inv[8];
#pragma unroll
        for (int r = 0; r < 8; r++) inv[r] = ginv[r];
        float* aout = attn_out + ((size_t)h << 20) + ((size_t)a0 << 10);
#pragma unroll
        for (int t = 0; t < 4; t++) {
            int b = tid + t * 256;
#pragma unroll
            for (int r = 0; r < 8; r++)
                __stcs(&aout[((size_t)r << 10) + b], lv[t][r] * inv[r]);
        }

        // V phase (fp16 V): thread (bg, d4), bg = tid>>2 in [0,64), d4 = tid&3
        int d4 = tid & 3;
        int bg = tid >> 2;
        float4 acc[8];
#pragma unroll
        for (int r = 0; r < 8; r++) acc[r] = make_float4(0.f, 0.f, 0.f, 0.f);
        const __half* V16h = g_V16 + h * 16384;
#pragma unroll 4
        for (int t = 0; t < 16; t++) {
            int b = bg + t * 64;
            // 4 halves = 8B at V16h[b*16 + d4*4]
            float hv = 0.f; (void)hv;
            uint2 raw = *(const uint2*)(V16h + b * 16 + d4 * 4);
            __half2 h01 = *(__half2*)&raw.x;
            __half2 h23 = *(__half2*)&raw.y;
            float2 v01 = __half22float2(h01);
            float2 v23 = __half22float2(h23);
            float4 v4 = make_float4(v01.x, v01.y, v23.x, v23.y);
#pragma unroll
            for (int r = 0; r < 8; r++) {
                float e = probs[r][b];
                acc[r].x += e * v4.x; acc[r].y += e * v4.y;
                acc[r].z += e * v4.z; acc[r].w += e * v4.w;
            }
        }
#pragma unroll
        for (int r = 0; r < 8; r++) {
#pragma unroll
            for (int o = 16; o >= 4; o >>= 1) {
                acc[r].x += __shfl_xor_sync(~0u, acc[r].x, o);
                acc[r].y += __shfl_xor_sync(~0u, acc[r].y, o);
                acc[r].z += __shfl_xor_sync(~0u, acc[r].z, o);
                acc[r].w += __shfl_xor_sync(~0u, acc[r].w, o);
            }
        }
        if (lane < 4) {
#pragma unroll
            for (int r = 0; r < 8; r++) part4[wid][r][d4] = acc[r];
        }
        __syncthreads();
        if (tid < 128) {
            int r = tid >> 4, d = tid & 15;
            int dq = d >> 2, cmp = d & 3;
            float s = 0.f;
#pragma unroll
            for (int w = 0; w < 8; w++) s += ((const float*)&part4[w][r][dq])[cmp];
            rowbuf[r * D_HEAD + d] = s * ginv[r];
        }
        __syncthreads();

        // Fused out-projection: out[n, :] = rowbuf @ Wout.T via g_WT (WT[k][c]).
        {
            int c4 = tid & 31;
            int kh = tid >> 5;
            float4 mv = make_float4(0.f, 0.f, 0.f, 0.f);
#pragma unroll
            for (int kk = 0; kk < 16; kk++) {
                int k = kh * 16 + kk;
                float rv = rowbuf[k];
                float4 w4 = *(const float4*)(g_WT + k * C_DIM + c4 * 4);
                mv.x += rv * w4.x; mv.y += rv * w4.y;
                mv.z += rv * w4.z; mv.w += rv * w4.w;
            }
            partmv[kh][c4] = mv;
        }
        __syncthreads();
        if (tid < 32) {
            float4 s4 = make_float4(0.f, 0.f, 0.f, 0.f);
#pragma unroll
            for (int kh = 0; kh < 8; kh++) {
                float4 p = partmv[kh][tid];
                s4.x += p.x; s4.y += p.y; s4.z += p.z; s4.w += p.w;
            }
            int n = h * 128 + ag;
            *(float4*)(out + (size_t)n * C_DIM + tid * 4) = s4;
        }
    }
}

// ---------------------------------------------------------------------------
extern "C" void kernel_launch(void* const* d_in, const int* in_sizes, int n_in,
                              void* d_out, int out_size) {
    const float* x      = (const float*)d_in[0];
    const float* sign   = (const float*)d_in[1];
    const float* weight = (const float*)d_in[2];
    const float* Wq     = (const float*)d_in[3];
    const float* Wk     = (const float*)d_in[4];
    const float* Wv     = (const float*)d_in[5];
    const float* Wout   = (const float*)d_in[6];
    const float* Wpos   = (const float*)d_in[7];
    const float* bpos   = (const float*)d_in[8];
    const float* conv_w = (const float*)d_in[9];
    const float* conv_b = (const float*)d_in[10];
    const float* param  = (const float*)d_in[11];
    const int*   seq    = (const int*)d_in[12];
    const int*   ei     = (const int*)d_in[13];

    float* out  = (float*)d_out;              // [1024, 128]
    float* attn = out + N_NODES * C_DIM;      // [1, 8, 1024, 1024]

    const int P_SMEM = SEQ_MAX * C_DIM * (int)sizeof(__half);  // 128KB dynamic
    static bool attr_set = false;
    if (!attr_set) {
        cudaFuncSetAttribute(attn_kernel,
                             cudaFuncAttributeMaxDynamicSharedMemorySize, P_SMEM);
        attr_set = true;
    }

    zero_conv_kernel<<<NN / 4 / 256, 256>>>();
    scatter_conv_kernel<<<E_EDGES / 256, 256>>>(ei, sign, weight, conv_w);
    qkvp_gemm_kernel<<<dim3(16, 2, 5), 256>>>(x, Wq, Wk, Wv, Wpos, bpos, Wout);
    attn_kernel<<<ATTN_BLOCKS, 256, P_SMEM>>>(seq, param, conv_b, attn, out);
}